// round 13
// baseline (speedup 1.0000x reference)
#include <cuda_runtime.h>
#include <cuda_fp16.h>
#include <cstdint>

#define OMEGA_ENC 0.01f
#define HD   64
#define LATD 32
#define SXF  68
#define YST  72
#define W2R  72
#define N0MAX 4096
#define N1MAX 1024
#define ETMAX (20480 + 10240)

// ---------------- scratch ----------------
__device__ float  g_acc0[N0MAX*HD];
__device__ float  g_acc1[N1MAX*HD];
__device__ float  g_h1[N0MAX*HD];
__device__ float  g_pool[N0MAX*HD];
__device__ int    g_kflag[N0MAX];
__device__ float4 g_feat[ETMAX];
__device__ int    g_src[ETMAX];
__device__ int    g_dst[ETMAX];
__device__ float  g_Yn[N0MAX*YST];
__device__ __half g_Bt[2][4096];
__device__ float  g_w2p[2][W2R*SXF];

// ---------------- helpers ----------------
__device__ __forceinline__ uint32_t smem_u32(const void* p){
    uint32_t a;
    asm("{ .reg .u64 t; cvta.to.shared.u64 t, %1; cvt.u32.u64 %0, t; }" : "=r"(a) : "l"(p));
    return a;
}
__device__ __forceinline__ uint32_t packh2(float v0, float v1){
    __half2 h = __floats2half2_rn(v0, v1);
    return *reinterpret_cast<uint32_t*>(&h);
}
__device__ __forceinline__ void mma16816(float* d, const uint32_t* a, uint32_t b0, uint32_t b1){
    asm volatile("mma.sync.aligned.m16n8k16.row.col.f32.f16.f16.f32 "
        "{%0,%1,%2,%3}, {%4,%5,%6,%7}, {%8,%9}, {%0,%1,%2,%3};"
        : "+f"(d[0]), "+f"(d[1]), "+f"(d[2]), "+f"(d[3])
        : "r"(a[0]), "r"(a[1]), "r"(a[2]), "r"(a[3]), "r"(b0), "r"(b1));
}

// ---------------- fused setup ----------------
__device__ __forceinline__ void geo_one(const int* ei, int E, int Etot,
                                        const float* pos, int off, int eg){
    if (eg >= Etot) return;
    int src, dst;
    float f0 = 0.f, f1 = 0.f, f2 = 0.f;
    if (eg < E){
        src = ei[eg]; dst = ei[E+eg];
        float rx = pos[dst*3+0]-pos[src*3+0];
        float ry = pos[dst*3+1]-pos[src*3+1];
        float rz = pos[dst*3+2]-pos[src*3+2];
        if (!(rx == 0.f && ry == 0.f && rz == 0.f)){
            float rho = sqrtf(rx*rx+ry*ry+rz*rz);
            float th  = atan2f(ry, rx);
            float ratio = fminf(fmaxf(rz/rho, -1.f), 1.f);
            float ph  = asinf(ratio);
            const float inv_pi = 0.3183098861837907f;
            f0 = rho; f1 = th*inv_pi; f2 = ph*inv_pi;
        }
    } else { src = eg - E; dst = src; }
    g_feat[off+eg] = make_float4(f0, f1, f2, 0.f);
    g_src[off+eg] = src; g_dst[off+eg] = dst;
}

__global__ void k_setup(
    const float* __restrict__ w1a, const float* __restrict__ w1b,
    const float* __restrict__ w2a, const float* __restrict__ w2b,
    const float* __restrict__ b2a, const float* __restrict__ b2b,
    const int* __restrict__ ei0, int E0, int Et0, const float* __restrict__ pos0,
    const int* __restrict__ ei1, int E1, int Et1, const float* __restrict__ pos1,
    int N0, int nbB, int nbBW, int nbBWG, int nbBWGG)
{
    int b = blockIdx.x, tid = threadIdx.x;
    if (b < nbB){                                   // ---- B tiles ----
        int i = b*256 + tid;
        int conv = i >> 12, j = i & 4095;
        int group = j >> 6, rc = j & 63;
        int kh = group & 1, gnt = group >> 1;
        int k2 = gnt >> 3, nt = gnt & 7;
        int r = rc >> 3, c = rc & 7;
        int h = k2*16 + kh*8 + r;
        int n = nt*8 + c;
        const float* w1 = conv ? w1b : w1a;
        g_Bt[conv][j] = __float2half_rn(0.1f * w1[h*HD + n]);
    } else if (b < nbBW){                           // ---- padded w2 ----
        int i = (b - nbB)*256 + tid;
        if (i >= 2*W2R*SXF) return;
        int conv = i / (W2R*SXF), j = i % (W2R*SXF);
        int k = j / SXF, f = j % SXF;
        const float* w2 = conv ? w2b : w2a;
        const float* b2 = conv ? b2b : b2a;
        float v = 0.f;
        if (f < 67){
            if (k < 64) v = w2[k*67 + f];
            else if (k == 64) v = b2[f];
        }
        g_w2p[conv][j] = v;
    } else if (b < nbBWG){                          // ---- geometry conv0 ----
        geo_one(ei0, E0, Et0, pos0, 0, (b - nbBW)*256 + tid);
    } else if (b < nbBWGG){                         // ---- geometry conv1 ----
        geo_one(ei1, E1, Et1, pos1, Et0, (b - nbBWG)*256 + tid);
    } else {                                        // ---- zero keep flags ----
        int n = (b - nbBWGG)*256 + tid;
        if (n < N0) g_kflag[n] = 0;
    }
}

// ---------------- encoder + per-node Y + keep-flag set ----------------
__global__ __launch_bounds__(256) void k_encY(
    const float* __restrict__ x, const float* __restrict__ pos,
    const float* __restrict__ w, const float* __restrict__ b,
    const float* __restrict__ w2p, int N, const int* __restrict__ keep, int N1){
    __shared__ __align__(16) float w2s[65*SXF];
    __shared__ __align__(16) float xs[4][SXF];
    int tid = threadIdx.x;
    for (int i = tid; i < 65*SXF; i += 256) w2s[i] = w2p[i];
    {   // set keep flags (setup already zeroed them; setup<->encY is ordered)
        int j = blockIdx.x*256 + tid;
        if (j < N1) g_kflag[keep[j]] = 1;
    }
    int node = tid >> 6, ch = tid & 63;
    int gn = blockIdx.x*4 + node;
    if (gn < N){
        float s = b[ch];
        #pragma unroll
        for (int f = 0; f < 8; f++) s += x[gn*8+f]*w[f*HD+ch];
        xs[node][ch] = sinf(OMEGA_ENC*s);
        g_acc0[gn*HD+ch] = 0.f;
        if (ch < 3) xs[node][HD+ch] = pos[gn*3+ch];
        if (ch == 3) xs[node][67] = 0.f;
    }
    __syncthreads();
    if (gn < N){
        const float4* xr = (const float4*)xs[node];
        const float4* wr = (const float4*)&w2s[ch*SXF];
        float y = 0.f;
        #pragma unroll
        for (int q = 0; q < 17; q++){
            float4 a = xr[q], bb = wr[q];
            y += a.x*bb.x + a.y*bb.y + a.z*bb.z + a.w*bb.w;
        }
        g_Yn[gn*YST + ch] = y;
        if (ch == 0){
            const float4* br = (const float4*)&w2s[64*SXF];
            float eb = 0.f;
            #pragma unroll
            for (int q = 0; q < 17; q++){
                float4 a = xr[q], bb = br[q];
                eb += a.x*bb.x + a.y*bb.y + a.z*bb.z + a.w*bb.w;
            }
            g_Yn[gn*YST + 64] = eb;
        }
    }
}

// ---------------- pooled gather + per-node Y (+acc1 init) ----------------
__global__ __launch_bounds__(128) void k_xf1Y(
    const int* __restrict__ keep, const float* __restrict__ pos1,
    const float* __restrict__ w2p){
    __shared__ __align__(16) float xs[SXF];
    int j = blockIdx.x, t = threadIdx.x;
    if (t < 64){
        xs[t] = g_pool[keep[j]*HD + t];
        g_acc1[j*HD+t] = 0.f;
    } else if (t < 67) xs[t] = pos1[j*3 + (t-64)];
    else if (t == 67) xs[67] = 0.f;
    __syncthreads();
    if (t < 65){
        const float4* xr = (const float4*)xs;
        const float4* wr = (const float4*)(w2p + t*SXF);
        float y = 0.f;
        #pragma unroll
        for (int q = 0; q < 17; q++){
            float4 a = xr[q], bb = wr[q];
            y += a.x*bb.x + a.y*bb.y + a.z*bb.z + a.w*bb.w;
        }
        g_Yn[j*YST + t] = y;
    }
}

// ---------------- HMMA conv: B fragments resident in registers ----------------
__global__ __launch_bounds__(128, 3) void k_convTC(
    const float* __restrict__ w0, const float* __restrict__ b0,
    const float* __restrict__ b1, const __half* __restrict__ Bt,
    int Etot, int ntiles, int off, float* __restrict__ acc)
{
    __shared__ __align__(16) __half smB[4096];
    __shared__ __align__(16) float4 sw4[64];
    __shared__ __align__(8)  float2 sc8[64];
    __shared__ __align__(8)  float sdel[64];
    __shared__ float sb1[64];

    const int tid = threadIdx.x;
    {
        const uint4* s = (const uint4*)Bt;
        uint4* d = (uint4*)smB;
        #pragma unroll
        for (int i = 0; i < 4; i++) d[tid + 128*i] = s[tid + 128*i];
    }
    if (tid < 64){
        float dd = 0.1f*w0[192+tid];
        sdel[tid] = dd;
        sb1[tid]  = 0.1f*b1[tid];
        sw4[tid]  = make_float4(0.1f*w0[tid], 0.1f*w0[64+tid],
                                0.1f*w0[128+tid], 0.1f*b0[tid]);
        float e8 = 8.f*dd;
        sc8[tid] = make_float2(cosf(e8), sinf(e8));
    }

    const int w = tid >> 5, l = tid & 31, g = l >> 2, t = l & 3;
    const int e  = w >> 1;
    const int cb = 32*(w & 1);
    const uint32_t lm_base = smem_u32(smB) +
        (uint32_t)(((((l >> 3) & 1)*64) + (l & 7)*8) * 2);
    const float cf = (float)(cb + g);

    __syncthreads();

    // preload ALL B fragments into registers (constant across tiles)
    uint32_t Bf0[32], Bf1[32];
    #pragma unroll
    for (int k2 = 0; k2 < 4; k2++){
        uint32_t lma = lm_base + (uint32_t)(k2*8)*256u;
        #pragma unroll
        for (int nt = 0; nt < 8; nt++){
            asm volatile("ldmatrix.sync.aligned.m8n8.x2.trans.shared.b16 "
                         "{%0,%1}, [%2];"
                         : "=r"(Bf0[k2*8+nt]), "=r"(Bf1[k2*8+nt]) : "r"(lma));
            lma += 256u;
        }
    }

    for (int tile = blockIdx.x; tile < ntiles; tile += gridDim.x){
        int eg = 2*tile + e;
        bool val = (eg < Etot);
        float4 ft = val ? g_feat[off+eg] : make_float4(0.f,0.f,0.f,0.f);

        float d[2][8][4];
        #pragma unroll
        for (int s = 0; s < 2; s++)
            #pragma unroll
            for (int n = 0; n < 8; n++)
                #pragma unroll
                for (int q = 0; q < 4; q++) d[s][n][q] = 0.f;

        #pragma unroll
        for (int k2 = 0; k2 < 4; k2++){
            const int hA = 2*t + 16*k2;
            uint32_t aH[2][4];
            #pragma unroll
            for (int j = 0; j < 2; j++){
                int hp = hA + 8*j;
                float4 s0 = sw4[hp], s1 = sw4[hp+1];
                float2 r0 = sc8[hp], r1 = sc8[hp+1];
                float2 dl = *(const float2*)&sdel[hp];
                float base0 = fmaf(ft.x, s0.x, fmaf(ft.y, s0.y, fmaf(ft.z, s0.z, s0.w)));
                float base1 = fmaf(ft.x, s1.x, fmaf(ft.y, s1.y, fmaf(ft.z, s1.z, s1.w)));
                float a0 = fmaf(cf, dl.x, base0);
                float a1 = fmaf(cf, dl.y, base1);
                float sA0 = __sinf(a0), cA0 = __cosf(a0);
                float sA1 = __sinf(a1), cA1 = __cosf(a1);
                float sB0 = fmaf(sA0, r0.x,  cA0*r0.y);
                float cB0 = fmaf(cA0, r0.x, -sA0*r0.y);
                float sB1 = fmaf(sA1, r1.x,  cA1*r1.y);
                float cB1 = fmaf(cA1, r1.x, -sA1*r1.y);
                float sC0 = fmaf(sB0, r0.x,  cB0*r0.y);
                float cC0 = fmaf(cB0, r0.x, -sB0*r0.y);
                float sC1 = fmaf(sB1, r1.x,  cB1*r1.y);
                float cC1 = fmaf(cB1, r1.x, -sB1*r1.y);
                float sD0 = fmaf(sC0, r0.x,  cC0*r0.y);
                float sD1 = fmaf(sC1, r1.x,  cC1*r1.y);
                aH[0][2*j+0] = packh2(sA0, sA1);
                aH[0][2*j+1] = packh2(sB0, sB1);
                aH[1][2*j+0] = packh2(sC0, sC1);
                aH[1][2*j+1] = packh2(sD0, sD1);
            }
            #pragma unroll
            for (int nt = 0; nt < 8; nt++){
                mma16816(d[0][nt], aH[0], Bf0[k2*8+nt], Bf1[k2*8+nt]);
                mma16816(d[1][nt], aH[1], Bf0[k2*8+nt], Bf1[k2*8+nt]);
            }
        }

        // ---- epilogue ----
        int sn = val ? g_src[off+eg] : 0;
        const float* yrow = &g_Yn[sn*YST];
        float m00 = 0.f, m01 = 0.f, m10 = 0.f, m11 = 0.f;
        #pragma unroll
        for (int nt = 0; nt < 8; nt++){
            int col = 2*t + 8*nt;
            float2 bv = *(const float2*)&sb1[col];
            float2 yv = val ? *(const float2*)&yrow[col] : make_float2(0.f, 0.f);
            m00 += __sinf(d[0][nt][0]+bv.x)*yv.x + __sinf(d[0][nt][1]+bv.y)*yv.y;
            m01 += __sinf(d[0][nt][2]+bv.x)*yv.x + __sinf(d[0][nt][3]+bv.y)*yv.y;
            m10 += __sinf(d[1][nt][0]+bv.x)*yv.x + __sinf(d[1][nt][1]+bv.y)*yv.y;
            m11 += __sinf(d[1][nt][2]+bv.x)*yv.x + __sinf(d[1][nt][3]+bv.y)*yv.y;
        }
        m00 += __shfl_xor_sync(~0u, m00, 1); m00 += __shfl_xor_sync(~0u, m00, 2);
        m01 += __shfl_xor_sync(~0u, m01, 1); m01 += __shfl_xor_sync(~0u, m01, 2);
        m10 += __shfl_xor_sync(~0u, m10, 1); m10 += __shfl_xor_sync(~0u, m10, 2);
        m11 += __shfl_xor_sync(~0u, m11, 1); m11 += __shfl_xor_sync(~0u, m11, 2);
        if (t == 0 && val){
            int dst = g_dst[off+eg];
            float eb = yrow[64];
            atomicAdd(&acc[dst*HD + cb + g     ], m00 + eb);
            atomicAdd(&acc[dst*HD + cb + g + 8 ], m01 + eb);
            atomicAdd(&acc[dst*HD + cb + g + 16], m10 + eb);
            atomicAdd(&acc[dst*HD + cb + g + 24], m11 + eb);
        }
    }
}

// ---------------- post0 (h1 + pool self-init) ----------------
__global__ void k_post0(const float* __restrict__ acc, const float* __restrict__ bias){
    int i = blockIdx.x*blockDim.x + threadIdx.x;
    float v = sinf(OMEGA_ENC*(acc[i] + bias[i & 63]));
    g_h1[i] = v;
    g_pool[i] = (__float_as_uint(v) == 0x80000000u) ? 0.f : v;
}
__device__ __forceinline__ void atomicMaxF(float* addr, float v){
    if (__float_as_uint(v) == 0x80000000u) v = 0.f;
    if (v >= 0.f) atomicMax((int*)addr, __float_as_int(v));
    else          atomicMin((unsigned int*)addr, __float_as_uint(v));
}
__global__ void k_pool(int E){
    int idx = blockIdx.x*blockDim.x + threadIdx.x;
    int e = idx >> 6, c = idx & 63;
    if (e >= E) return;
    int dst = g_dst[e];
    if (!g_kflag[dst]) return;          // only keep-rows are ever read
    atomicMaxF(&g_pool[dst*HD + c], g_h1[g_src[e]*HD + c]);
}
// ---------------- fused post(acc1) + final linear ----------------
__global__ __launch_bounds__(64) void k_fin(
    const float* __restrict__ acc, const float* __restrict__ bias,
    const float* __restrict__ w, const float* __restrict__ b,
    float* __restrict__ out){
    __shared__ float h2s[HD];
    int j = blockIdx.x, t = threadIdx.x;
    h2s[t] = sinf(OMEGA_ENC*(acc[j*HD+t] + bias[t]));
    __syncthreads();
    if (t < LATD){
        float s = b[t];
        #pragma unroll
        for (int c = 0; c < HD; c++) s += h2s[c]*w[c*LATD+t];
        out[j*LATD+t] = sinf(OMEGA_ENC*s);
    }
}

// ---------------- launch ----------------
extern "C" void kernel_launch(void* const* d_in, const int* in_sizes, int n_in,
                              void* d_out, int out_size){
    int iPos = 1, iEi = 2;
    if (in_sizes[1] == in_sizes[0]) { iEi = 1; iPos = 2; }

    const float* x      = (const float*)d_in[0];
    const float* pos    = (const float*)d_in[iPos];
    const int*   ei     = (const int*)  d_in[iEi];
    const int*   ei1    = (const int*)  d_in[3];
    const float* pos1   = (const float*)d_in[4];
    const int*   keep   = (const int*)  d_in[5];
    const float* lin0_w = (const float*)d_in[6];
    const float* lin0_b = (const float*)d_in[7];
    const float* lin1_w = (const float*)d_in[8];
    const float* lin1_b = (const float*)d_in[9];
    const float* c0p[7]; for (int i = 0; i < 7; i++) c0p[i] = (const float*)d_in[10+i];
    const float* c1p[7]; for (int i = 0; i < 7; i++) c1p[i] = (const float*)d_in[17+i];

    int N0 = in_sizes[0] / 8;
    int E0 = in_sizes[iEi] / 2;
    int N1 = in_sizes[5];
    int E1 = in_sizes[3] / 2;
    int Et0 = E0 + N0, Et1 = E1 + N1;
    int nt0 = (Et0 + 1)/2, nt1 = (Et1 + 1)/2;
    float* out = (float*)d_out;

    float *acc0, *acc1, *w2p;
    __half* bt;
    cudaGetSymbolAddress((void**)&acc0, g_acc0);
    cudaGetSymbolAddress((void**)&acc1, g_acc1);
    cudaGetSymbolAddress((void**)&bt,   g_Bt);
    cudaGetSymbolAddress((void**)&w2p,  g_w2p);

    int g0 = nt0 < 444 ? nt0 : 444;   // 3 CTAs/SM
    int g1 = nt1 < 444 ? nt1 : 444;

    int nbB  = 32;
    int nbW  = (2*W2R*SXF + 255)/256;
    int nbG0 = (Et0 + 255)/256;
    int nbG1 = (Et1 + 255)/256;
    int nbF  = (N0 + 255)/256;
    int nbBW = nbB + nbW, nbBWG = nbBW + nbG0, nbBWGG = nbBWG + nbG1;
    k_setup<<<nbBWGG + nbF, 256>>>(c0p[2], c1p[2], c0p[4], c1p[4], c0p[5], c1p[5],
                                   ei, E0, Et0, pos, ei1, E1, Et1, pos1,
                                   N0, nbB, nbBW, nbBWG, nbBWGG);
    k_encY <<<(N0 + 3)/4, 256>>>(x, pos, lin0_w, lin0_b, w2p, N0, keep, N1);

    // ---- conv0 ----
    k_convTC<<<g0, 128>>>(c0p[0], c0p[1], c0p[3], bt, Et0, nt0, 0, acc0);
    k_post0 <<<(N0*HD)/256, 256>>>(acc0, c0p[6]);

    // ---- pool ----
    k_pool<<<(E0*HD + 255)/256, 256>>>(E0);
    k_xf1Y<<<N1, 128>>>(keep, pos1, w2p + W2R*SXF);

    // ---- conv1 ----
    k_convTC<<<g1, 128>>>(c1p[0], c1p[1], c1p[3], bt + 4096, Et1, nt1, Et0, acc1);

    k_fin<<<N1, 64>>>(acc1, c1p[6], lin1_w, lin1_b, out);
}

// round 14
// speedup vs baseline: 1.0349x; 1.0349x over previous
#include <cuda_runtime.h>
#include <cuda_fp16.h>
#include <cstdint>

#define OMEGA_ENC 0.01f
#define HD   64
#define LATD 32
#define SXF  68
#define YST  72
#define W2R  72
#define N0MAX 4096
#define N1MAX 1024
#define ETMAX (20480 + 10240)

// ---------------- scratch ----------------
__device__ float  g_acc0[N0MAX*HD];
__device__ float  g_acc1[N1MAX*HD];
__device__ float  g_h1[N0MAX*HD];
__device__ float  g_pool[N0MAX*HD];
__device__ int    g_kflag[N0MAX];
__device__ float4 g_feat[ETMAX];
__device__ int    g_src[ETMAX];
__device__ int    g_dst[ETMAX];
__device__ float  g_Yn[N0MAX*YST];
__device__ __half g_Bt[2][4096];
__device__ float  g_w2p[2][W2R*SXF];

// ---------------- helpers ----------------
__device__ __forceinline__ uint32_t smem_u32(const void* p){
    uint32_t a;
    asm("{ .reg .u64 t; cvta.to.shared.u64 t, %1; cvt.u32.u64 %0, t; }" : "=r"(a) : "l"(p));
    return a;
}
__device__ __forceinline__ uint32_t packh2(float v0, float v1){
    __half2 h = __floats2half2_rn(v0, v1);
    return *reinterpret_cast<uint32_t*>(&h);
}
__device__ __forceinline__ void mma16816(float* d, const uint32_t* a, uint32_t b0, uint32_t b1){
    asm volatile("mma.sync.aligned.m16n8k16.row.col.f32.f16.f16.f32 "
        "{%0,%1,%2,%3}, {%4,%5,%6,%7}, {%8,%9}, {%0,%1,%2,%3};"
        : "+f"(d[0]), "+f"(d[1]), "+f"(d[2]), "+f"(d[3])
        : "r"(a[0]), "r"(a[1]), "r"(a[2]), "r"(a[3]), "r"(b0), "r"(b1));
}

// ---------------- fused setup ----------------
__device__ __forceinline__ void geo_one(const int* ei, int E, int Etot,
                                        const float* pos, int off, int eg){
    if (eg >= Etot) return;
    int src, dst;
    float f0 = 0.f, f1 = 0.f, f2 = 0.f;
    if (eg < E){
        src = ei[eg]; dst = ei[E+eg];
        float rx = pos[dst*3+0]-pos[src*3+0];
        float ry = pos[dst*3+1]-pos[src*3+1];
        float rz = pos[dst*3+2]-pos[src*3+2];
        if (!(rx == 0.f && ry == 0.f && rz == 0.f)){
            float rho = sqrtf(rx*rx+ry*ry+rz*rz);
            float th  = atan2f(ry, rx);
            float ratio = fminf(fmaxf(rz/rho, -1.f), 1.f);
            float ph  = asinf(ratio);
            const float inv_pi = 0.3183098861837907f;
            f0 = rho; f1 = th*inv_pi; f2 = ph*inv_pi;
        }
    } else { src = eg - E; dst = src; }
    g_feat[off+eg] = make_float4(f0, f1, f2, 0.f);
    g_src[off+eg] = src; g_dst[off+eg] = dst;
}

__global__ void k_setup(
    const float* __restrict__ w1a, const float* __restrict__ w1b,
    const float* __restrict__ w2a, const float* __restrict__ w2b,
    const float* __restrict__ b2a, const float* __restrict__ b2b,
    const int* __restrict__ ei0, int E0, int Et0, const float* __restrict__ pos0,
    const int* __restrict__ ei1, int E1, int Et1, const float* __restrict__ pos1,
    int N0, int nbB, int nbBW, int nbBWG, int nbBWGG)
{
    int b = blockIdx.x, tid = threadIdx.x;
    if (b < nbB){                                   // ---- B tiles ----
        int i = b*256 + tid;
        int conv = i >> 12, j = i & 4095;
        int group = j >> 6, rc = j & 63;
        int kh = group & 1, gnt = group >> 1;
        int k2 = gnt >> 3, nt = gnt & 7;
        int r = rc >> 3, c = rc & 7;
        int h = k2*16 + kh*8 + r;
        int n = nt*8 + c;
        const float* w1 = conv ? w1b : w1a;
        g_Bt[conv][j] = __float2half_rn(0.1f * w1[h*HD + n]);
    } else if (b < nbBW){                           // ---- padded w2 ----
        int i = (b - nbB)*256 + tid;
        if (i >= 2*W2R*SXF) return;
        int conv = i / (W2R*SXF), j = i % (W2R*SXF);
        int k = j / SXF, f = j % SXF;
        const float* w2 = conv ? w2b : w2a;
        const float* b2 = conv ? b2b : b2a;
        float v = 0.f;
        if (f < 67){
            if (k < 64) v = w2[k*67 + f];
            else if (k == 64) v = b2[f];
        }
        g_w2p[conv][j] = v;
    } else if (b < nbBWG){                          // ---- geometry conv0 ----
        geo_one(ei0, E0, Et0, pos0, 0, (b - nbBW)*256 + tid);
    } else if (b < nbBWGG){                         // ---- geometry conv1 ----
        geo_one(ei1, E1, Et1, pos1, Et0, (b - nbBWG)*256 + tid);
    } else {                                        // ---- zero keep flags ----
        int n = (b - nbBWGG)*256 + tid;
        if (n < N0) g_kflag[n] = 0;
    }
}

// ---------------- encoder + per-node Y + keep-flag set ----------------
__global__ __launch_bounds__(256) void k_encY(
    const float* __restrict__ x, const float* __restrict__ pos,
    const float* __restrict__ w, const float* __restrict__ b,
    const float* __restrict__ w2p, int N, const int* __restrict__ keep, int N1){
    __shared__ __align__(16) float w2s[65*SXF];
    __shared__ __align__(16) float xs[4][SXF];
    int tid = threadIdx.x;
    for (int i = tid; i < 65*SXF; i += 256) w2s[i] = w2p[i];
    {   // set keep flags (setup zeroed them; setup -> encY is stream-ordered)
        int j = blockIdx.x*256 + tid;
        if (j < N1) g_kflag[keep[j]] = 1;
    }
    int node = tid >> 6, ch = tid & 63;
    int gn = blockIdx.x*4 + node;
    if (gn < N){
        float s = b[ch];
        #pragma unroll
        for (int f = 0; f < 8; f++) s += x[gn*8+f]*w[f*HD+ch];
        xs[node][ch] = sinf(OMEGA_ENC*s);
        g_acc0[gn*HD+ch] = 0.f;
        if (ch < 3) xs[node][HD+ch] = pos[gn*3+ch];
        if (ch == 3) xs[node][67] = 0.f;
    }
    __syncthreads();
    if (gn < N){
        const float4* xr = (const float4*)xs[node];
        const float4* wr = (const float4*)&w2s[ch*SXF];
        float y = 0.f;
        #pragma unroll
        for (int q = 0; q < 17; q++){
            float4 a = xr[q], bb = wr[q];
            y += a.x*bb.x + a.y*bb.y + a.z*bb.z + a.w*bb.w;
        }
        g_Yn[gn*YST + ch] = y;
        if (ch == 0){
            const float4* br = (const float4*)&w2s[64*SXF];
            float eb = 0.f;
            #pragma unroll
            for (int q = 0; q < 17; q++){
                float4 a = xr[q], bb = br[q];
                eb += a.x*bb.x + a.y*bb.y + a.z*bb.z + a.w*bb.w;
            }
            g_Yn[gn*YST + 64] = eb;
        }
    }
}

// ---------------- pooled gather + per-node Y (+acc1 init) ----------------
__global__ __launch_bounds__(128) void k_xf1Y(
    const int* __restrict__ keep, const float* __restrict__ pos1,
    const float* __restrict__ w2p){
    __shared__ __align__(16) float xs[SXF];
    int j = blockIdx.x, t = threadIdx.x;
    if (t < 64){
        xs[t] = g_pool[keep[j]*HD + t];
        g_acc1[j*HD+t] = 0.f;
    } else if (t < 67) xs[t] = pos1[j*3 + (t-64)];
    else if (t == 67) xs[67] = 0.f;
    __syncthreads();
    if (t < 65){
        const float4* xr = (const float4*)xs;
        const float4* wr = (const float4*)(w2p + t*SXF);
        float y = 0.f;
        #pragma unroll
        for (int q = 0; q < 17; q++){
            float4 a = xr[q], bb = wr[q];
            y += a.x*bb.x + a.y*bb.y + a.z*bb.z + a.w*bb.w;
        }
        g_Yn[j*YST + t] = y;
    }
}

// ---------------- HMMA conv (R12 config: ldmatrix in-loop, occ 4) -------------
__global__ __launch_bounds__(128, 4) void k_convTC(
    const float* __restrict__ w0, const float* __restrict__ b0,
    const float* __restrict__ b1, const __half* __restrict__ Bt,
    int Etot, int ntiles, int off, float* __restrict__ acc)
{
    __shared__ __align__(16) __half smB[4096];
    __shared__ __align__(16) float4 sw4[64];
    __shared__ __align__(8)  float2 sc8[64];
    __shared__ __align__(8)  float sdel[64];
    __shared__ float sb1[64];

    const int tid = threadIdx.x;
    {
        const uint4* s = (const uint4*)Bt;
        uint4* d = (uint4*)smB;
        #pragma unroll
        for (int i = 0; i < 4; i++) d[tid + 128*i] = s[tid + 128*i];
    }
    if (tid < 64){
        float dd = 0.1f*w0[192+tid];
        sdel[tid] = dd;
        sb1[tid]  = 0.1f*b1[tid];
        sw4[tid]  = make_float4(0.1f*w0[tid], 0.1f*w0[64+tid],
                                0.1f*w0[128+tid], 0.1f*b0[tid]);
        float e8 = 8.f*dd;
        sc8[tid] = make_float2(cosf(e8), sinf(e8));
    }

    const int w = tid >> 5, l = tid & 31, g = l >> 2, t = l & 3;
    const int e  = w >> 1;
    const int cb = 32*(w & 1);
    const uint32_t lm_base = smem_u32(smB) +
        (uint32_t)(((((l >> 3) & 1)*64) + (l & 7)*8) * 2);
    const float cf = (float)(cb + g);

    __syncthreads();

    for (int tile = blockIdx.x; tile < ntiles; tile += gridDim.x){
        int eg = 2*tile + e;
        bool val = (eg < Etot);
        float4 ft = val ? g_feat[off+eg] : make_float4(0.f,0.f,0.f,0.f);

        float d[2][8][4];
        #pragma unroll
        for (int s = 0; s < 2; s++)
            #pragma unroll
            for (int n = 0; n < 8; n++)
                #pragma unroll
                for (int q = 0; q < 4; q++) d[s][n][q] = 0.f;

        #pragma unroll
        for (int k2 = 0; k2 < 4; k2++){
            const int hA = 2*t + 16*k2;
            uint32_t aH[2][4];
            #pragma unroll
            for (int j = 0; j < 2; j++){
                int hp = hA + 8*j;
                float4 s0 = sw4[hp], s1 = sw4[hp+1];
                float2 r0 = sc8[hp], r1 = sc8[hp+1];
                float2 dl = *(const float2*)&sdel[hp];
                float base0 = fmaf(ft.x, s0.x, fmaf(ft.y, s0.y, fmaf(ft.z, s0.z, s0.w)));
                float base1 = fmaf(ft.x, s1.x, fmaf(ft.y, s1.y, fmaf(ft.z, s1.z, s1.w)));
                float a0 = fmaf(cf, dl.x, base0);
                float a1 = fmaf(cf, dl.y, base1);
                float sA0 = __sinf(a0), cA0 = __cosf(a0);
                float sA1 = __sinf(a1), cA1 = __cosf(a1);
                float sB0 = fmaf(sA0, r0.x,  cA0*r0.y);
                float cB0 = fmaf(cA0, r0.x, -sA0*r0.y);
                float sB1 = fmaf(sA1, r1.x,  cA1*r1.y);
                float cB1 = fmaf(cA1, r1.x, -sA1*r1.y);
                float sC0 = fmaf(sB0, r0.x,  cB0*r0.y);
                float cC0 = fmaf(cB0, r0.x, -sB0*r0.y);
                float sC1 = fmaf(sB1, r1.x,  cB1*r1.y);
                float cC1 = fmaf(cB1, r1.x, -sB1*r1.y);
                float sD0 = fmaf(sC0, r0.x,  cC0*r0.y);
                float sD1 = fmaf(sC1, r1.x,  cC1*r1.y);
                aH[0][2*j+0] = packh2(sA0, sA1);
                aH[0][2*j+1] = packh2(sB0, sB1);
                aH[1][2*j+0] = packh2(sC0, sC1);
                aH[1][2*j+1] = packh2(sD0, sD1);
            }
            uint32_t lma = lm_base + (uint32_t)(k2*8)*256u;
            #pragma unroll
            for (int nt = 0; nt < 8; nt++){
                uint32_t r0, r1;
                asm volatile("ldmatrix.sync.aligned.m8n8.x2.trans.shared.b16 "
                             "{%0,%1}, [%2];"
                             : "=r"(r0), "=r"(r1) : "r"(lma));
                lma += 256u;
                mma16816(d[0][nt], aH[0], r0, r1);
                mma16816(d[1][nt], aH[1], r0, r1);
            }
        }

        // ---- epilogue ----
        int sn = val ? g_src[off+eg] : 0;
        const float* yrow = &g_Yn[sn*YST];
        float m00 = 0.f, m01 = 0.f, m10 = 0.f, m11 = 0.f;
        #pragma unroll
        for (int nt = 0; nt < 8; nt++){
            int col = 2*t + 8*nt;
            float2 bv = *(const float2*)&sb1[col];
            float2 yv = val ? *(const float2*)&yrow[col] : make_float2(0.f, 0.f);
            m00 += __sinf(d[0][nt][0]+bv.x)*yv.x + __sinf(d[0][nt][1]+bv.y)*yv.y;
            m01 += __sinf(d[0][nt][2]+bv.x)*yv.x + __sinf(d[0][nt][3]+bv.y)*yv.y;
            m10 += __sinf(d[1][nt][0]+bv.x)*yv.x + __sinf(d[1][nt][1]+bv.y)*yv.y;
            m11 += __sinf(d[1][nt][2]+bv.x)*yv.x + __sinf(d[1][nt][3]+bv.y)*yv.y;
        }
        m00 += __shfl_xor_sync(~0u, m00, 1); m00 += __shfl_xor_sync(~0u, m00, 2);
        m01 += __shfl_xor_sync(~0u, m01, 1); m01 += __shfl_xor_sync(~0u, m01, 2);
        m10 += __shfl_xor_sync(~0u, m10, 1); m10 += __shfl_xor_sync(~0u, m10, 2);
        m11 += __shfl_xor_sync(~0u, m11, 1); m11 += __shfl_xor_sync(~0u, m11, 2);
        if (t == 0 && val){
            int dst = g_dst[off+eg];
            float eb = yrow[64];
            atomicAdd(&acc[dst*HD + cb + g     ], m00 + eb);
            atomicAdd(&acc[dst*HD + cb + g + 8 ], m01 + eb);
            atomicAdd(&acc[dst*HD + cb + g + 16], m10 + eb);
            atomicAdd(&acc[dst*HD + cb + g + 24], m11 + eb);
        }
    }
}

// ---------------- post0 (h1 + pool self-init) ----------------
__global__ void k_post0(const float* __restrict__ acc, const float* __restrict__ bias){
    int i = blockIdx.x*blockDim.x + threadIdx.x;
    float v = sinf(OMEGA_ENC*(acc[i] + bias[i & 63]));
    g_h1[i] = v;
    g_pool[i] = (__float_as_uint(v) == 0x80000000u) ? 0.f : v;
}
__device__ __forceinline__ void atomicMaxF(float* addr, float v){
    if (__float_as_uint(v) == 0x80000000u) v = 0.f;
    if (v >= 0.f) atomicMax((int*)addr, __float_as_int(v));
    else          atomicMin((unsigned int*)addr, __float_as_uint(v));
}
__global__ void k_pool(int E){
    int idx = blockIdx.x*blockDim.x + threadIdx.x;
    int e = idx >> 6, c = idx & 63;
    if (e >= E) return;
    int dst = g_dst[e];
    if (!g_kflag[dst]) return;          // only keep-rows are ever read
    atomicMaxF(&g_pool[dst*HD + c], g_h1[g_src[e]*HD + c]);
}
// ---------------- fused post(acc1) + final linear ----------------
__global__ __launch_bounds__(64) void k_fin(
    const float* __restrict__ acc, const float* __restrict__ bias,
    const float* __restrict__ w, const float* __restrict__ b,
    float* __restrict__ out){
    __shared__ float h2s[HD];
    int j = blockIdx.x, t = threadIdx.x;
    h2s[t] = sinf(OMEGA_ENC*(acc[j*HD+t] + bias[t]));
    __syncthreads();
    if (t < LATD){
        float s = b[t];
        #pragma unroll
        for (int c = 0; c < HD; c++) s += h2s[c]*w[c*LATD+t];
        out[j*LATD+t] = sinf(OMEGA_ENC*s);
    }
}

// ---------------- launch ----------------
extern "C" void kernel_launch(void* const* d_in, const int* in_sizes, int n_in,
                              void* d_out, int out_size){
    int iPos = 1, iEi = 2;
    if (in_sizes[1] == in_sizes[0]) { iEi = 1; iPos = 2; }

    const float* x      = (const float*)d_in[0];
    const float* pos    = (const float*)d_in[iPos];
    const int*   ei     = (const int*)  d_in[iEi];
    const int*   ei1    = (const int*)  d_in[3];
    const float* pos1   = (const float*)d_in[4];
    const int*   keep   = (const int*)  d_in[5];
    const float* lin0_w = (const float*)d_in[6];
    const float* lin0_b = (const float*)d_in[7];
    const float* lin1_w = (const float*)d_in[8];
    const float* lin1_b = (const float*)d_in[9];
    const float* c0p[7]; for (int i = 0; i < 7; i++) c0p[i] = (const float*)d_in[10+i];
    const float* c1p[7]; for (int i = 0; i < 7; i++) c1p[i] = (const float*)d_in[17+i];

    int N0 = in_sizes[0] / 8;
    int E0 = in_sizes[iEi] / 2;
    int N1 = in_sizes[5];
    int E1 = in_sizes[3] / 2;
    int Et0 = E0 + N0, Et1 = E1 + N1;
    int nt0 = (Et0 + 1)/2, nt1 = (Et1 + 1)/2;
    float* out = (float*)d_out;

    float *acc0, *acc1, *w2p;
    __half* bt;
    cudaGetSymbolAddress((void**)&acc0, g_acc0);
    cudaGetSymbolAddress((void**)&acc1, g_acc1);
    cudaGetSymbolAddress((void**)&bt,   g_Bt);
    cudaGetSymbolAddress((void**)&w2p,  g_w2p);

    int g0 = nt0 < 592 ? nt0 : 592;   // 4 CTAs/SM
    int g1 = nt1 < 592 ? nt1 : 592;

    int nbB  = 32;
    int nbW  = (2*W2R*SXF + 255)/256;
    int nbG0 = (Et0 + 255)/256;
    int nbG1 = (Et1 + 255)/256;
    int nbF  = (N0 + 255)/256;
    int nbBW = nbB + nbW, nbBWG = nbBW + nbG0, nbBWGG = nbBWG + nbG1;
    k_setup<<<nbBWGG + nbF, 256>>>(c0p[2], c1p[2], c0p[4], c1p[4], c0p[5], c1p[5],
                                   ei, E0, Et0, pos, ei1, E1, Et1, pos1,
                                   N0, nbB, nbBW, nbBWG, nbBWGG);
    k_encY <<<(N0 + 3)/4, 256>>>(x, pos, lin0_w, lin0_b, w2p, N0, keep, N1);

    // ---- conv0 ----
    k_convTC<<<g0, 128>>>(c0p[0], c0p[1], c0p[3], bt, Et0, nt0, 0, acc0);
    k_post0 <<<(N0*HD)/256, 256>>>(acc0, c0p[6]);

    // ---- pool ----
    k_pool<<<(E0*HD + 255)/256, 256>>>(E0);
    k_xf1Y<<<N1, 128>>>(keep, pos1, w2p + W2R*SXF);

    // ---- conv1 ----
    k_convTC<<<g1, 128>>>(c1p[0], c1p[1], c1p[3], bt + 4096, Et1, nt1, Et0, acc1);

    k_fin<<<N1, 64>>>(acc1, c1p[6], lin1_w, lin1_b, out);
}